// round 1
// baseline (speedup 1.0000x reference)
#include <cuda_runtime.h>
#include <math.h>
#include <stdint.h>

// Problem shapes (fixed)
#define NTOK 4096          // B*S = 2*2048
#define HDIM 2048
#define NEXP 16
#define TOPK 4
#define IMOE 1408
#define ISH  5632
#define NSLOT (NTOK*TOPK)  // 16384 (always fully populated: sum of expert counts == N*K)

// ---------------- scratch (device globals; no allocations allowed) ----------------
__device__ float g_Gr[(size_t)NSLOT * IMOE];  // routed gate -> then t = silu(g)*u
__device__ float g_Ur[(size_t)NSLOT * IMOE];  // routed up
__device__ float g_Dr[(size_t)NSLOT * HDIM];  // routed down output per slot (unweighted)
__device__ float g_Gs[(size_t)NTOK * ISH];    // shared gate -> then t
__device__ float g_Us[(size_t)NTOK * ISH];    // shared up
__device__ float g_Ss[(size_t)NTOK * HDIM];   // shared expert output
__device__ float g_sg[NTOK];                  // sigmoid gate per token
__device__ int   g_topk_idx[NSLOT];
__device__ float g_topk_w[NSLOT];
__device__ int   g_cnt[NEXP];
__device__ int   g_off[NEXP + 1];
__device__ int   g_fill[NEXP];
__device__ int   g_tok[NSLOT];                // expert-sorted token ids
__device__ int   g_slotof[NSLOT];             // (n,k) -> slot position

// ---------------- small kernels ----------------
__global__ void init_kernel() {
    int t = threadIdx.x;
    if (t < NEXP) { g_cnt[t] = 0; g_fill[t] = 0; }
}

// One block per token: logits (16 dots of 2048), softmax fp32, top-4, renorm.
__global__ void router_kernel(const float* __restrict__ h, const float* __restrict__ rw) {
    __shared__ float sh[HDIM];
    __shared__ float lg[NEXP];
    int n = blockIdx.x;
    int tid = threadIdx.x;      // 128 threads
    const float* hp = h + (size_t)n * HDIM;
    for (int i = tid; i < HDIM; i += 128) sh[i] = hp[i];
    __syncthreads();
    int w = tid >> 5, lane = tid & 31;
    for (int e = w; e < NEXP; e += 4) {
        const float* r = rw + (size_t)e * HDIM;
        float s = 0.f;
        for (int i = lane; i < HDIM; i += 32) s += sh[i] * r[i];
        #pragma unroll
        for (int o = 16; o; o >>= 1) s += __shfl_xor_sync(0xffffffff, s, o);
        if (lane == 0) lg[e] = s;
    }
    __syncthreads();
    if (tid == 0) {
        float m = -1e30f;
        for (int e = 0; e < NEXP; e++) m = fmaxf(m, lg[e]);
        float p[NEXP]; float sum = 0.f;
        for (int e = 0; e < NEXP; e++) { p[e] = expf(lg[e] - m); sum += p[e]; }
        float inv = 1.f / sum;
        for (int e = 0; e < NEXP; e++) p[e] *= inv;
        int   idx[TOPK]; float val[TOPK]; float tot = 0.f;
        for (int k = 0; k < TOPK; k++) {
            float best = -1.f; int bi = 0;
            for (int e = 0; e < NEXP; e++) if (p[e] > best) { best = p[e]; bi = e; }
            idx[k] = bi; val[k] = best; p[bi] = -2.f; tot += best;
        }
        float invt = 1.f / fmaxf(tot, 1e-9f);
        for (int k = 0; k < TOPK; k++) {
            g_topk_idx[n * TOPK + k] = idx[k];
            g_topk_w[n * TOPK + k]   = val[k] * invt;
            atomicAdd(&g_cnt[idx[k]], 1);
        }
    }
}

__global__ void offsets_kernel() {
    if (threadIdx.x == 0) {
        int acc = 0;
        for (int e = 0; e < NEXP; e++) { g_off[e] = acc; acc += g_cnt[e]; }
        g_off[NEXP] = acc;
    }
}

__global__ void scatter_kernel() {
    int i = blockIdx.x * blockDim.x + threadIdx.x;
    if (i >= NSLOT) return;
    int e = g_topk_idx[i];
    int pos = g_off[e] + atomicAdd(&g_fill[e], 1);
    g_tok[pos]  = i / TOPK;
    g_slotof[i] = pos;
}

// ---------------- SGEMM: C[M,N] = A[M,K] @ B[K,N], row-major, fp32 SIMT ----------------
// EXPERT: blockIdx.z selects expert; M/base from g_off; B += e*K*N; C rows at base+row.
// GATHER: A row index taken from g_tok[base+row] (rows of `h`), else A row = base+row.
template <bool GATHER, bool EXPERT>
__global__ void __launch_bounds__(256, 2)
sgemm_kernel(const float* __restrict__ A, const float* __restrict__ B,
             float* __restrict__ C, int Ncols, int K, int Mtotal)
{
    __shared__ float As[16][128];   // As[k][m]
    __shared__ float Bs[16][128];   // Bs[k][n]

    int base = 0, M;
    const float* Bp = B;
    if (EXPERT) {
        int e = blockIdx.z;
        base  = g_off[e];
        M     = g_off[e + 1] - base;
        Bp    = B + (size_t)e * (size_t)K * (size_t)Ncols;
    } else {
        M = Mtotal;
    }
    int m0 = blockIdx.y * 128;
    if (m0 >= M) return;
    int n0 = blockIdx.x * 128;

    int tid = threadIdx.x;
    // A tile load mapping: 128 rows x 16 k, 2 float4 per thread
    int ar0 = tid >> 2;              // 0..63
    int ak  = (tid & 3) * 4;         // 0,4,8,12
    int row0 = m0 + ar0, row1 = row0 + 64;
    bool v0 = row0 < M, v1 = row1 < M;
    int gr0 = 0, gr1 = 0;
    if (v0) gr0 = GATHER ? g_tok[base + row0] : (base + row0);
    if (v1) gr1 = GATHER ? g_tok[base + row1] : (base + row1);
    const float* ap0 = A + (size_t)gr0 * K + ak;
    const float* ap1 = A + (size_t)gr1 * K + ak;
    // B tile load mapping: 16 k x 128 n, 2 float4 per thread
    int bk0 = tid >> 5;              // 0..7
    int bn  = (tid & 31) * 4;
    const float* bp0 = Bp + (size_t)bk0 * Ncols + n0 + bn;
    const float* bp1 = Bp + (size_t)(bk0 + 8) * Ncols + n0 + bn;

    int ty = tid >> 4, tx = tid & 15;
    float c[8][8];
    #pragma unroll
    for (int i = 0; i < 8; i++)
        #pragma unroll
        for (int j = 0; j < 8; j++) c[i][j] = 0.f;

    for (int k0 = 0; k0 < K; k0 += 16) {
        float4 va0 = v0 ? *(const float4*)(ap0 + k0) : make_float4(0.f, 0.f, 0.f, 0.f);
        float4 va1 = v1 ? *(const float4*)(ap1 + k0) : make_float4(0.f, 0.f, 0.f, 0.f);
        float4 vb0 = *(const float4*)(bp0 + (size_t)k0 * Ncols);
        float4 vb1 = *(const float4*)(bp1 + (size_t)k0 * Ncols);

        __syncthreads();   // previous iteration's compute done
        As[ak + 0][ar0] = va0.x; As[ak + 1][ar0] = va0.y;
        As[ak + 2][ar0] = va0.z; As[ak + 3][ar0] = va0.w;
        As[ak + 0][ar0 + 64] = va1.x; As[ak + 1][ar0 + 64] = va1.y;
        As[ak + 2][ar0 + 64] = va1.z; As[ak + 3][ar0 + 64] = va1.w;
        *(float4*)&Bs[bk0][bn]     = vb0;
        *(float4*)&Bs[bk0 + 8][bn] = vb1;
        __syncthreads();

        #pragma unroll
        for (int k = 0; k < 16; k++) {
            float4 aA = *(const float4*)&As[k][ty * 8];
            float4 aB = *(const float4*)&As[k][ty * 8 + 4];
            float4 bA = *(const float4*)&Bs[k][tx * 8];
            float4 bB = *(const float4*)&Bs[k][tx * 8 + 4];
            float a[8] = {aA.x, aA.y, aA.z, aA.w, aB.x, aB.y, aB.z, aB.w};
            float b[8] = {bA.x, bA.y, bA.z, bA.w, bB.x, bB.y, bB.z, bB.w};
            #pragma unroll
            for (int i = 0; i < 8; i++)
                #pragma unroll
                for (int j = 0; j < 8; j++)
                    c[i][j] = fmaf(a[i], b[j], c[i][j]);
        }
    }

    #pragma unroll
    for (int i = 0; i < 8; i++) {
        int row = m0 + ty * 8 + i;
        if (row < M) {
            float* cp = C + (size_t)(base + row) * Ncols + n0 + tx * 8;
            *(float4*)cp       = make_float4(c[i][0], c[i][1], c[i][2], c[i][3]);
            *(float4*)(cp + 4) = make_float4(c[i][4], c[i][5], c[i][6], c[i][7]);
        }
    }
}

// t = silu(g) * u, elementwise (in-place into g)
__global__ void silu_mul_kernel(float* __restrict__ g, const float* __restrict__ u, size_t nelem) {
    size_t i = ((size_t)blockIdx.x * blockDim.x + threadIdx.x) * 4;
    if (i >= nelem) return;
    float4 gv = *(const float4*)(g + i);
    float4 uv = *(const float4*)(u + i);
    float4 o;
    o.x = gv.x / (1.f + expf(-gv.x)) * uv.x;
    o.y = gv.y / (1.f + expf(-gv.y)) * uv.y;
    o.z = gv.z / (1.f + expf(-gv.z)) * uv.z;
    o.w = gv.w / (1.f + expf(-gv.w)) * uv.w;
    *(float4*)(g + i) = o;
}

// sg[n] = sigmoid(h[n,:] . sh_gate_w)   (one warp per token)
__global__ void sgate_kernel(const float* __restrict__ h, const float* __restrict__ w) {
    int gt = blockIdx.x * blockDim.x + threadIdx.x;
    int n = gt >> 5, lane = gt & 31;
    if (n >= NTOK) return;
    const float* hp = h + (size_t)n * HDIM;
    float s = 0.f;
    for (int i = lane; i < HDIM; i += 32) s = fmaf(hp[i], w[i], s);
    #pragma unroll
    for (int o = 16; o; o >>= 1) s += __shfl_xor_sync(0xffffffff, s, o);
    if (lane == 0) g_sg[n] = 1.f / (1.f + expf(-s));
}

// out[n,:] = sum_k w_k * Dr[slot_k,:] + sg[n] * Ss[n,:]
__global__ void combine_kernel(float* __restrict__ out) {
    int n = blockIdx.x;
    __shared__ int   ss[TOPK];
    __shared__ float ww[TOPK];
    __shared__ float sgv;
    if (threadIdx.x < TOPK) {
        ss[threadIdx.x] = g_slotof[n * TOPK + threadIdx.x];
        ww[threadIdx.x] = g_topk_w[n * TOPK + threadIdx.x];
    }
    if (threadIdx.x == 0) sgv = g_sg[n];
    __syncthreads();
    const float4* d0 = (const float4*)(g_Dr + (size_t)ss[0] * HDIM);
    const float4* d1 = (const float4*)(g_Dr + (size_t)ss[1] * HDIM);
    const float4* d2 = (const float4*)(g_Dr + (size_t)ss[2] * HDIM);
    const float4* d3 = (const float4*)(g_Dr + (size_t)ss[3] * HDIM);
    const float4* sh = (const float4*)(g_Ss + (size_t)n * HDIM);
    float4* op = (float4*)(out + (size_t)n * HDIM);
    float w0 = ww[0], w1 = ww[1], w2 = ww[2], w3 = ww[3], s = sgv;
    for (int j = threadIdx.x; j < HDIM / 4; j += blockDim.x) {
        float4 a = d0[j], b = d1[j], c = d2[j], d = d3[j], e = sh[j];
        float4 r;
        r.x = w0 * a.x + w1 * b.x + w2 * c.x + w3 * d.x + s * e.x;
        r.y = w0 * a.y + w1 * b.y + w2 * c.y + w3 * d.y + s * e.y;
        r.z = w0 * a.z + w1 * b.z + w2 * c.z + w3 * d.z + s * e.z;
        r.w = w0 * a.w + w1 * b.w + w2 * c.w + w3 * d.w + s * e.w;
        op[j] = r;
    }
}

// ---------------- launch ----------------
extern "C" void kernel_launch(void* const* d_in, const int* in_sizes, int n_in,
                              void* d_out, int out_size) {
    const float* h   = (const float*)d_in[0];   // [N, H]
    const float* rw  = (const float*)d_in[1];   // [E, H]
    const float* wg  = (const float*)d_in[2];   // [E, H, I]
    const float* wu  = (const float*)d_in[3];   // [E, H, I]
    const float* wd  = (const float*)d_in[4];   // [E, I, H]
    const float* shg = (const float*)d_in[5];   // [H, ISH]
    const float* shu = (const float*)d_in[6];   // [H, ISH]
    const float* shd = (const float*)d_in[7];   // [ISH, H]
    const float* sgw = (const float*)d_in[8];   // [H, 1]
    float* out = (float*)d_out;

    float *pGr, *pUr, *pDr, *pGs, *pUs, *pSs;
    cudaGetSymbolAddress((void**)&pGr, g_Gr);
    cudaGetSymbolAddress((void**)&pUr, g_Ur);
    cudaGetSymbolAddress((void**)&pDr, g_Dr);
    cudaGetSymbolAddress((void**)&pGs, g_Gs);
    cudaGetSymbolAddress((void**)&pUs, g_Us);
    cudaGetSymbolAddress((void**)&pSs, g_Ss);

    // Router pipeline
    init_kernel<<<1, 32>>>();
    router_kernel<<<NTOK, 128>>>(h, rw);
    offsets_kernel<<<1, 1>>>();
    scatter_kernel<<<NSLOT / 256, 256>>>();

    // Routed experts: gate & up (gathered A), SwiGLU, down
    dim3 gGU(IMOE / 128, 32, NEXP);
    sgemm_kernel<true,  true><<<gGU, 256>>>(h, wg, pGr, IMOE, HDIM, 0);
    sgemm_kernel<true,  true><<<gGU, 256>>>(h, wu, pUr, IMOE, HDIM, 0);
    {
        size_t ne = (size_t)NSLOT * IMOE;
        silu_mul_kernel<<<(unsigned)(ne / 4 / 256), 256>>>(pGr, pUr, ne);
    }
    dim3 gD(HDIM / 128, 32, NEXP);
    sgemm_kernel<false, true><<<gD, 256>>>(pGr, wd, pDr, HDIM, IMOE, 0);

    // Shared expert
    dim3 gS1(ISH / 128, NTOK / 128, 1);
    sgemm_kernel<false, false><<<gS1, 256>>>(h, shg, pGs, ISH, HDIM, NTOK);
    sgemm_kernel<false, false><<<gS1, 256>>>(h, shu, pUs, ISH, HDIM, NTOK);
    {
        size_t ne = (size_t)NTOK * ISH;
        silu_mul_kernel<<<(unsigned)(ne / 4 / 256), 256>>>(pGs, pUs, ne);
    }
    dim3 gS2(HDIM / 128, NTOK / 128, 1);
    sgemm_kernel<false, false><<<gS2, 256>>>(pGs, shd, pSs, HDIM, ISH, NTOK);

    sgate_kernel<<<(NTOK * 32 + 255) / 256, 256>>>(h, sgw);

    // Final combine
    combine_kernel<<<NTOK, 256>>>(out);
}

// round 4
// speedup vs baseline: 2.7475x; 2.7475x over previous
#include <cuda_runtime.h>
#include <math.h>
#include <stdint.h>

// Problem shapes (fixed)
#define NTOK 4096
#define HDIM 2048
#define NEXP 16
#define TOPK 4
#define IMOE 1408
#define ISH  5632
#define NSLOT (NTOK*TOPK)

// ---------------- scratch (device globals) ----------------
__device__ float g_Gr[(size_t)NSLOT * IMOE];
__device__ float g_Ur[(size_t)NSLOT * IMOE];
__device__ float g_Dr[(size_t)NSLOT * HDIM];
__device__ float g_Gs[(size_t)NTOK * ISH];
__device__ float g_Us[(size_t)NTOK * ISH];
__device__ float g_Ss[(size_t)NTOK * HDIM];
__device__ float g_sg[NTOK];
__device__ int   g_topk_idx[NSLOT];
__device__ float g_topk_w[NSLOT];
__device__ int   g_cnt[NEXP];
__device__ int   g_off[NEXP + 1];
__device__ int   g_fill[NEXP];
__device__ int   g_tok[NSLOT];
__device__ int   g_slotof[NSLOT];

// ---------------- helpers ----------------
#define SWZ(off) ((off) ^ (((off) >> 3) & 0x70))

__device__ __forceinline__ uint32_t smem_u32(const void* p) {
    uint32_t a;
    asm("{ .reg .u64 t; cvta.to.shared.u64 t, %1; cvt.u32.u64 %0, t; }" : "=r"(a) : "l"(p));
    return a;
}

__device__ __forceinline__ void ldsm4(uint32_t* r, uint32_t addr) {
    asm volatile("ldmatrix.sync.aligned.m8n8.x4.shared.b16 {%0,%1,%2,%3}, [%4];"
                 : "=r"(r[0]), "=r"(r[1]), "=r"(r[2]), "=r"(r[3]) : "r"(addr));
}

__device__ __forceinline__ void mma_tf32(float* c, const uint32_t* a, uint32_t b0, uint32_t b1) {
    asm volatile("mma.sync.aligned.m16n8k8.row.col.f32.tf32.tf32.f32 "
                 "{%0,%1,%2,%3}, {%4,%5,%6,%7}, {%8,%9}, {%0,%1,%2,%3};"
                 : "+f"(c[0]), "+f"(c[1]), "+f"(c[2]), "+f"(c[3])
                 : "r"(a[0]), "r"(a[1]), "r"(a[2]), "r"(a[3]), "r"(b0), "r"(b1));
}

// ---------------- small kernels (validated in R1) ----------------
__global__ void init_kernel() {
    int t = threadIdx.x;
    if (t < NEXP) { g_cnt[t] = 0; g_fill[t] = 0; }
}

__global__ void router_kernel(const float* __restrict__ h, const float* __restrict__ rw) {
    __shared__ float sh[HDIM];
    __shared__ float lg[NEXP];
    int n = blockIdx.x;
    int tid = threadIdx.x;
    const float* hp = h + (size_t)n * HDIM;
    for (int i = tid; i < HDIM; i += 128) sh[i] = hp[i];
    __syncthreads();
    int w = tid >> 5, lane = tid & 31;
    for (int e = w; e < NEXP; e += 4) {
        const float* r = rw + (size_t)e * HDIM;
        float s = 0.f;
        for (int i = lane; i < HDIM; i += 32) s += sh[i] * r[i];
        #pragma unroll
        for (int o = 16; o; o >>= 1) s += __shfl_xor_sync(0xffffffff, s, o);
        if (lane == 0) lg[e] = s;
    }
    __syncthreads();
    if (tid == 0) {
        float m = -1e30f;
        for (int e = 0; e < NEXP; e++) m = fmaxf(m, lg[e]);
        float p[NEXP]; float sum = 0.f;
        for (int e = 0; e < NEXP; e++) { p[e] = expf(lg[e] - m); sum += p[e]; }
        float inv = 1.f / sum;
        for (int e = 0; e < NEXP; e++) p[e] *= inv;
        int idx[TOPK]; float val[TOPK]; float tot = 0.f;
        for (int k = 0; k < TOPK; k++) {
            float best = -1.f; int bi = 0;
            for (int e = 0; e < NEXP; e++) if (p[e] > best) { best = p[e]; bi = e; }
            idx[k] = bi; val[k] = best; p[bi] = -2.f; tot += best;
        }
        float invt = 1.f / fmaxf(tot, 1e-9f);
        for (int k = 0; k < TOPK; k++) {
            g_topk_idx[n * TOPK + k] = idx[k];
            g_topk_w[n * TOPK + k]   = val[k] * invt;
            atomicAdd(&g_cnt[idx[k]], 1);
        }
    }
}

__global__ void offsets_kernel() {
    if (threadIdx.x == 0) {
        int acc = 0;
        for (int e = 0; e < NEXP; e++) { g_off[e] = acc; acc += g_cnt[e]; }
        g_off[NEXP] = acc;
    }
}

__global__ void scatter_kernel() {
    int i = blockIdx.x * blockDim.x + threadIdx.x;
    if (i >= NSLOT) return;
    int e = g_topk_idx[i];
    int pos = g_off[e] + atomicAdd(&g_fill[e], 1);
    g_tok[pos]  = i / TOPK;
    g_slotof[i] = pos;
}

// ---------------- tf32 mma.sync GEMM ----------------
// C[M,Ncols] = A[M,K] @ B[K,Ncols]. Block tile 128x128xK32, 8 warps (2x4),
// warp tile 64x32 via m16n8k8 tf32 mma. As[m][k] / Bs[n][k] in SW128 rows,
// double-buffered. Inputs rounded fp32->tf32 via +0x1000 (truncation => RN).
template <bool GATHER, bool EXPERT>
__global__ void __launch_bounds__(256, 1)
mmagemm(const float* __restrict__ A, const float* __restrict__ B0, const float* __restrict__ B1,
        float* __restrict__ C0, float* __restrict__ C1, int Ncols, int K, int Mtot)
{
    extern __shared__ float smem_raw[];
    int tid = threadIdx.x, lane = tid & 31, wid = tid >> 5;
    int wm = wid >> 2, wn = wid & 3;   // 2 x 4 warp grid

    int e    = EXPERT ? blockIdx.z : 0;
    int base = EXPERT ? g_off[e] : 0;
    int M    = EXPERT ? (g_off[e + 1] - base) : Mtot;
    int m0   = blockIdx.y * 128;
    if (m0 >= M) return;
    int ntiles = Ncols / 128;
    int sel    = blockIdx.x / ntiles;
    long n0    = (long)(blockIdx.x % ntiles) * 128;
    const float* B = sel ? B1 : B0;
    if (EXPERT) B += (size_t)e * (size_t)K * (size_t)Ncols;
    float* C = sel ? C1 : C0;

    uint32_t sb = (smem_u32(smem_raw) + 1023u) & ~1023u;   // 1024-aligned tile base

    // ---- producer mapping: 2 threads per row (A) / per column (B), 16 k each
    int pr = tid >> 1;            // 0..127
    int kh = (tid & 1) * 16;      // k-half (floats)
    int rc = min(m0 + pr, M - 1);
    int arow = GATHER ? g_tok[base + rc] : (base + rc);
    const float* ap = A + (size_t)arow * K + kh;
    const float* bp = B + n0 + pr + (size_t)kh * Ncols;
    uint32_t prow = (uint32_t)(pr * 128 + (tid & 1) * 64);  // byte offset in tile

    int nit = K >> 5;
    uint4 aice[4];
    float bice[16];
    float acc[4][4][4];
    #pragma unroll
    for (int i = 0; i < 4; i++)
        #pragma unroll
        for (int j = 0; j < 4; j++)
            #pragma unroll
            for (int q = 0; q < 4; q++) acc[i][j][q] = 0.f;

    // prologue: load tile 0
    {
        const uint4* s = (const uint4*)ap;
        #pragma unroll
        for (int q = 0; q < 4; q++) aice[q] = s[q];
        #pragma unroll
        for (int kk = 0; kk < 16; kk++) bice[kk] = bp[(size_t)kk * Ncols];
    }
    // STS stage 0
    {
        uint32_t aB = sb, bB = sb + 16384;
        #pragma unroll
        for (int q = 0; q < 4; q++) {
            uint4 v = aice[q];
            v.x += 0x1000u; v.y += 0x1000u; v.z += 0x1000u; v.w += 0x1000u;
            uint32_t ad = aB + SWZ(prow + q * 16);
            asm volatile("st.shared.v4.b32 [%0], {%1,%2,%3,%4};"
                         :: "r"(ad), "r"(v.x), "r"(v.y), "r"(v.z), "r"(v.w));
        }
        #pragma unroll
        for (int q = 0; q < 4; q++) {
            uint32_t b0 = __float_as_uint(bice[4*q+0]) + 0x1000u;
            uint32_t b1 = __float_as_uint(bice[4*q+1]) + 0x1000u;
            uint32_t b2 = __float_as_uint(bice[4*q+2]) + 0x1000u;
            uint32_t b3 = __float_as_uint(bice[4*q+3]) + 0x1000u;
            uint32_t ad = bB + SWZ(prow + q * 16);
            asm volatile("st.shared.v4.b32 [%0], {%1,%2,%3,%4};"
                         :: "r"(ad), "r"(b0), "r"(b1), "r"(b2), "r"(b3));
        }
    }
    __syncthreads();

    for (int it = 0; it < nit; it++) {
        int s = it & 1;
        // prefetch next tile into registers (LDG latency hidden by mma below)
        if (it + 1 < nit) {
            const uint4* sa = (const uint4*)(ap + (size_t)(it + 1) * 32);
            #pragma unroll
            for (int q = 0; q < 4; q++) aice[q] = sa[q];
            const float* bq = bp + (size_t)(it + 1) * 32 * Ncols;
            #pragma unroll
            for (int kk = 0; kk < 16; kk++) bice[kk] = bq[(size_t)kk * Ncols];
        }
        // compute on stage s
        {
            uint32_t aB = sb + (uint32_t)s * 32768u;
            uint32_t bB = aB + 16384u;
            #pragma unroll
            for (int ks = 0; ks < 4; ks++) {
                uint32_t af[4][4];
                #pragma unroll
                for (int mf = 0; mf < 4; mf++) {
                    uint32_t row = (uint32_t)(wm * 64 + mf * 16 + (lane & 15));
                    uint32_t off = row * 128 + (uint32_t)ks * 32 + ((lane >> 4) * 16);
                    ldsm4(af[mf], aB + SWZ(off));
                }
                uint32_t bf[2][4];
                #pragma unroll
                for (int j = 0; j < 2; j++) {
                    uint32_t row = (uint32_t)(wn * 32 + j * 16 + (lane & 7) + ((lane >> 4) << 3));
                    uint32_t off = row * 128 + (uint32_t)ks * 32 + (((lane >> 3) & 1) * 16);
                    ldsm4(bf[j], bB + SWZ(off));
                }
                #pragma unroll
                for (int mf = 0; mf < 4; mf++)
                    #pragma unroll
                    for (int nf = 0; nf < 4; nf++)
                        mma_tf32(acc[mf][nf], af[mf], bf[nf >> 1][(nf & 1) * 2],
                                 bf[nf >> 1][(nf & 1) * 2 + 1]);
            }
        }
        // STS next tile into stage s^1
        if (it + 1 < nit) {
            uint32_t aB = sb + (uint32_t)(1 - s) * 32768u;
            uint32_t bB = aB + 16384u;
            #pragma unroll
            for (int q = 0; q < 4; q++) {
                uint4 v = aice[q];
                v.x += 0x1000u; v.y += 0x1000u; v.z += 0x1000u; v.w += 0x1000u;
                uint32_t ad = aB + SWZ(prow + q * 16);
                asm volatile("st.shared.v4.b32 [%0], {%1,%2,%3,%4};"
                             :: "r"(ad), "r"(v.x), "r"(v.y), "r"(v.z), "r"(v.w));
            }
            #pragma unroll
            for (int q = 0; q < 4; q++) {
                uint32_t b0 = __float_as_uint(bice[4*q+0]) + 0x1000u;
                uint32_t b1 = __float_as_uint(bice[4*q+1]) + 0x1000u;
                uint32_t b2 = __float_as_uint(bice[4*q+2]) + 0x1000u;
                uint32_t b3 = __float_as_uint(bice[4*q+3]) + 0x1000u;
                uint32_t ad = bB + SWZ(prow + q * 16);
                asm volatile("st.shared.v4.b32 [%0], {%1,%2,%3,%4};"
                             :: "r"(ad), "r"(b0), "r"(b1), "r"(b2), "r"(b3));
            }
        }
        __syncthreads();
    }

    // ---- epilogue: registers -> C global
    #pragma unroll
    for (int mf = 0; mf < 4; mf++) {
        int r0 = m0 + wm * 64 + mf * 16 + (lane >> 2);
        #pragma unroll
        for (int nf = 0; nf < 4; nf++) {
            long col = n0 + wn * 32 + nf * 8 + (lane & 3) * 2;
            float* cp = C + (size_t)(base + r0) * Ncols + col;
            if (r0 < M)     *(float2*)cp                       = make_float2(acc[mf][nf][0], acc[mf][nf][1]);
            if (r0 + 8 < M) *(float2*)(cp + (size_t)8 * Ncols) = make_float2(acc[mf][nf][2], acc[mf][nf][3]);
        }
    }
}

// ---------------- elementwise ----------------
__global__ void silu_mul_kernel(float* __restrict__ g, const float* __restrict__ u, size_t nelem) {
    size_t i = ((size_t)blockIdx.x * blockDim.x + threadIdx.x) * 4;
    if (i >= nelem) return;
    float4 gv = *(const float4*)(g + i);
    float4 uv = *(const float4*)(u + i);
    float4 o;
    o.x = gv.x / (1.f + expf(-gv.x)) * uv.x;
    o.y = gv.y / (1.f + expf(-gv.y)) * uv.y;
    o.z = gv.z / (1.f + expf(-gv.z)) * uv.z;
    o.w = gv.w / (1.f + expf(-gv.w)) * uv.w;
    *(float4*)(g + i) = o;
}

__global__ void sgate_kernel(const float* __restrict__ h, const float* __restrict__ w) {
    int gt = blockIdx.x * blockDim.x + threadIdx.x;
    int n = gt >> 5, lane = gt & 31;
    if (n >= NTOK) return;
    const float* hp = h + (size_t)n * HDIM;
    float s = 0.f;
    for (int i = lane; i < HDIM; i += 32) s = fmaf(hp[i], w[i], s);
    #pragma unroll
    for (int o = 16; o; o >>= 1) s += __shfl_xor_sync(0xffffffff, s, o);
    if (lane == 0) g_sg[n] = 1.f / (1.f + expf(-s));
}

__global__ void combine_kernel(float* __restrict__ out) {
    int n = blockIdx.x;
    __shared__ int   ss[TOPK];
    __shared__ float ww[TOPK];
    __shared__ float sgv;
    if (threadIdx.x < TOPK) {
        ss[threadIdx.x] = g_slotof[n * TOPK + threadIdx.x];
        ww[threadIdx.x] = g_topk_w[n * TOPK + threadIdx.x];
    }
    if (threadIdx.x == 0) sgv = g_sg[n];
    __syncthreads();
    const float4* d0 = (const float4*)(g_Dr + (size_t)ss[0] * HDIM);
    const float4* d1 = (const float4*)(g_Dr + (size_t)ss[1] * HDIM);
    const float4* d2 = (const float4*)(g_Dr + (size_t)ss[2] * HDIM);
    const float4* d3 = (const float4*)(g_Dr + (size_t)ss[3] * HDIM);
    const float4* sh = (const float4*)(g_Ss + (size_t)n * HDIM);
    float4* op = (float4*)(out + (size_t)n * HDIM);
    float w0 = ww[0], w1 = ww[1], w2 = ww[2], w3 = ww[3], s = sgv;
    for (int j = threadIdx.x; j < HDIM / 4; j += blockDim.x) {
        float4 a = d0[j], b = d1[j], c = d2[j], d = d3[j], e2 = sh[j];
        float4 r;
        r.x = w0 * a.x + w1 * b.x + w2 * c.x + w3 * d.x + s * e2.x;
        r.y = w0 * a.y + w1 * b.y + w2 * c.y + w3 * d.y + s * e2.y;
        r.z = w0 * a.z + w1 * b.z + w2 * c.z + w3 * d.z + s * e2.z;
        r.w = w0 * a.w + w1 * b.w + w2 * c.w + w3 * d.w + s * e2.w;
        op[j] = r;
    }
}

// ---------------- launch ----------------
extern "C" void kernel_launch(void* const* d_in, const int* in_sizes, int n_in,
                              void* d_out, int out_size) {
    const float* h   = (const float*)d_in[0];
    const float* rw  = (const float*)d_in[1];
    const float* wg  = (const float*)d_in[2];
    const float* wu  = (const float*)d_in[3];
    const float* wd  = (const float*)d_in[4];
    const float* shg = (const float*)d_in[5];
    const float* shu = (const float*)d_in[6];
    const float* shd = (const float*)d_in[7];
    const float* sgw = (const float*)d_in[8];
    float* out = (float*)d_out;

    float *pGr, *pUr, *pDr, *pGs, *pUs, *pSs;
    cudaGetSymbolAddress((void**)&pGr, g_Gr);
    cudaGetSymbolAddress((void**)&pUr, g_Ur);
    cudaGetSymbolAddress((void**)&pDr, g_Dr);
    cudaGetSymbolAddress((void**)&pGs, g_Gs);
    cudaGetSymbolAddress((void**)&pUs, g_Us);
    cudaGetSymbolAddress((void**)&pSs, g_Ss);

    const int SMB = 2 * 32768 + 1024;   // double buffer + alignment pad
    cudaFuncSetAttribute(mmagemm<true,  true >, cudaFuncAttributeMaxDynamicSharedMemorySize, SMB);
    cudaFuncSetAttribute(mmagemm<false, true >, cudaFuncAttributeMaxDynamicSharedMemorySize, SMB);
    cudaFuncSetAttribute(mmagemm<false, false>, cudaFuncAttributeMaxDynamicSharedMemorySize, SMB);

    // Router pipeline
    init_kernel<<<1, 32>>>();
    router_kernel<<<NTOK, 128>>>(h, rw);
    offsets_kernel<<<1, 1>>>();
    scatter_kernel<<<NSLOT / 256, 256>>>();

    // Routed experts: fused gate+up (gathered A), SwiGLU, down
    {
        dim3 g(2 * (IMOE / 128), 32, NEXP);   // (22, 32, 16)
        mmagemm<true, true><<<g, 256, SMB>>>(h, wg, wu, pGr, pUr, IMOE, HDIM, 0);
    }
    {
        size_t ne = (size_t)NSLOT * IMOE;
        silu_mul_kernel<<<(unsigned)(ne / 4 / 256), 256>>>(pGr, pUr, ne);
    }
    {
        dim3 g(HDIM / 128, 32, NEXP);         // (16, 32, 16)
        mmagemm<false, true><<<g, 256, SMB>>>(pGr, wd, wd, pDr, pDr, HDIM, IMOE, 0);
    }

    // Shared expert: fused gate+up, SwiGLU, down
    {
        dim3 g(2 * (ISH / 128), NTOK / 128, 1);   // (88, 32, 1)
        mmagemm<false, false><<<g, 256, SMB>>>(h, shg, shu, pGs, pUs, ISH, HDIM, NTOK);
    }
    {
        size_t ne = (size_t)NTOK * ISH;
        silu_mul_kernel<<<(unsigned)(ne / 4 / 256), 256>>>(pGs, pUs, ne);
    }
    {
        dim3 g(HDIM / 128, NTOK / 128, 1);    // (16, 32, 1)
        mmagemm<false, false><<<g, 256, SMB>>>(pGs, shd, shd, pSs, pSs, HDIM, ISH, NTOK);
    }

    sgate_kernel<<<(NTOK * 32 + 255) / 256, 256>>>(h, sgw);
    combine_kernel<<<NTOK, 256>>>(out);
}

// round 6
// speedup vs baseline: 3.4255x; 1.2468x over previous
#include <cuda_runtime.h>
#include <math.h>
#include <stdint.h>

// Problem shapes (fixed)
#define NTOK 4096
#define HDIM 2048
#define NEXP 16
#define TOPK 4
#define IMOE 1408
#define ISH  5632
#define NSLOT (NTOK*TOPK)

// ---------------- scratch (device globals) ----------------
__device__ float g_Gr[(size_t)NSLOT * IMOE];
__device__ float g_Ur[(size_t)NSLOT * IMOE];
__device__ float g_Dr[(size_t)NSLOT * HDIM];
__device__ float g_Gs[(size_t)NTOK * ISH];
__device__ float g_Us[(size_t)NTOK * ISH];
__device__ float g_Ss[(size_t)NTOK * HDIM];
__device__ float g_sg[NTOK];
__device__ int   g_topk_idx[NSLOT];
__device__ float g_topk_w[NSLOT];
__device__ int   g_cnt[NEXP];
__device__ int   g_off[NEXP + 1];
__device__ int   g_fill[NEXP];
__device__ int   g_tok[NSLOT];
__device__ int   g_slotof[NSLOT];
// pre-rounded (fp32 -> tf32-RN bit pattern) operand copies
__device__ float g_hr [(size_t)NTOK * HDIM];
__device__ float g_wg [(size_t)NEXP * HDIM * IMOE];
__device__ float g_wu [(size_t)NEXP * HDIM * IMOE];
__device__ float g_wd [(size_t)NEXP * IMOE * HDIM];
__device__ float g_shg[(size_t)HDIM * ISH];
__device__ float g_shu[(size_t)HDIM * ISH];
__device__ float g_shd[(size_t)ISH * HDIM];

// ---------------- helpers ----------------
#define SWZ(off) ((off) ^ (((off) >> 3) & 0x70))

__device__ __forceinline__ uint32_t smem_u32(const void* p) {
    uint32_t a;
    asm("{ .reg .u64 t; cvta.to.shared.u64 t, %1; cvt.u32.u64 %0, t; }" : "=r"(a) : "l"(p));
    return a;
}
__device__ __forceinline__ void ldsm4(uint32_t* r, uint32_t addr) {
    asm volatile("ldmatrix.sync.aligned.m8n8.x4.shared.b16 {%0,%1,%2,%3}, [%4];"
                 : "=r"(r[0]), "=r"(r[1]), "=r"(r[2]), "=r"(r[3]) : "r"(addr));
}
__device__ __forceinline__ void mma_tf32(float* c, const uint32_t* a, uint32_t b0, uint32_t b1) {
    asm volatile("mma.sync.aligned.m16n8k8.row.col.f32.tf32.tf32.f32 "
                 "{%0,%1,%2,%3}, {%4,%5,%6,%7}, {%8,%9}, {%0,%1,%2,%3};"
                 : "+f"(c[0]), "+f"(c[1]), "+f"(c[2]), "+f"(c[3])
                 : "r"(a[0]), "r"(a[1]), "r"(a[2]), "r"(a[3]), "r"(b0), "r"(b1));
}
__device__ __forceinline__ void cpa16(uint32_t dst, const void* src) {
    asm volatile("cp.async.cg.shared.global [%0], [%1], 16;" :: "r"(dst), "l"(src));
}
__device__ __forceinline__ void cpa4(uint32_t dst, const void* src) {
    asm volatile("cp.async.ca.shared.global [%0], [%1], 4;" :: "r"(dst), "l"(src));
}
#define CPA_COMMIT() asm volatile("cp.async.commit_group;" ::: "memory")
#define CPA_WAIT1()  asm volatile("cp.async.wait_group 1;" ::: "memory")

// ---------------- small kernels ----------------
__global__ void init_kernel() {
    int t = threadIdx.x;
    if (t < NEXP) { g_cnt[t] = 0; g_fill[t] = 0; }
}

__global__ void round_kernel(const float* __restrict__ src, float* __restrict__ dst) {
    size_t i = (size_t)blockIdx.x * blockDim.x + threadIdx.x;
    uint4 v = ((const uint4*)src)[i];
    v.x += 0x1000u; v.y += 0x1000u; v.z += 0x1000u; v.w += 0x1000u;
    ((uint4*)dst)[i] = v;
}

__global__ void router_kernel(const float* __restrict__ h, const float* __restrict__ rw) {
    __shared__ float sh[HDIM];
    __shared__ float lg[NEXP];
    int n = blockIdx.x;
    int tid = threadIdx.x;
    const float* hp = h + (size_t)n * HDIM;
    for (int i = tid; i < HDIM; i += 128) sh[i] = hp[i];
    __syncthreads();
    int w = tid >> 5, lane = tid & 31;
    for (int e = w; e < NEXP; e += 4) {
        const float* r = rw + (size_t)e * HDIM;
        float s = 0.f;
        for (int i = lane; i < HDIM; i += 32) s += sh[i] * r[i];
        #pragma unroll
        for (int o = 16; o; o >>= 1) s += __shfl_xor_sync(0xffffffff, s, o);
        if (lane == 0) lg[e] = s;
    }
    __syncthreads();
    if (tid == 0) {
        float m = -1e30f;
        for (int e = 0; e < NEXP; e++) m = fmaxf(m, lg[e]);
        float p[NEXP]; float sum = 0.f;
        for (int e = 0; e < NEXP; e++) { p[e] = expf(lg[e] - m); sum += p[e]; }
        float inv = 1.f / sum;
        for (int e = 0; e < NEXP; e++) p[e] *= inv;
        int idx[TOPK]; float val[TOPK]; float tot = 0.f;
        for (int k = 0; k < TOPK; k++) {
            float best = -1.f; int bi = 0;
            for (int e = 0; e < NEXP; e++) if (p[e] > best) { best = p[e]; bi = e; }
            idx[k] = bi; val[k] = best; p[bi] = -2.f; tot += best;
        }
        float invt = 1.f / fmaxf(tot, 1e-9f);
        for (int k = 0; k < TOPK; k++) {
            g_topk_idx[n * TOPK + k] = idx[k];
            g_topk_w[n * TOPK + k]   = val[k] * invt;
            atomicAdd(&g_cnt[idx[k]], 1);
        }
    }
}

__global__ void offsets_kernel() {
    if (threadIdx.x == 0) {
        int acc = 0;
        for (int e = 0; e < NEXP; e++) { g_off[e] = acc; acc += g_cnt[e]; }
        g_off[NEXP] = acc;
    }
}

__global__ void scatter_kernel() {
    int i = blockIdx.x * blockDim.x + threadIdx.x;
    if (i >= NSLOT) return;
    int e = g_topk_idx[i];
    int pos = g_off[e] + atomicAdd(&g_fill[e], 1);
    g_tok[pos]  = i / TOPK;
    g_slotof[i] = pos;
}

// ---------------- tf32 mma.sync GEMM, cp.async 3-stage ----------------
// C[M,Ncols] = A[M,K] @ B[K,Ncols]. Block tile 256x128x32, 8 warps (4x2),
// warp tile 64x64 via m16n8k8 tf32 mma. All operands pre-rounded to tf32-RN.
// Stage: As 256x(32k) = 32KB swizzled rows + Bs 128x(32k) = 16KB -> 48KB; 3 stages.
template <bool GATHER, bool EXPERT>
__global__ void __launch_bounds__(256, 1)
mmagemm(const float* __restrict__ A, const float* __restrict__ B0, const float* __restrict__ B1,
        float* __restrict__ C0, float* __restrict__ C1, int Ncols, int K, int Mtot)
{
    extern __shared__ char smraw[];
    constexpr uint32_t STG = 49152u;
    int tid = threadIdx.x, lane = tid & 31, wid = tid >> 5;
    int wm = wid >> 1, wn = wid & 1;   // 4 x 2 warp grid, warp tile 64x64

    int e    = EXPERT ? blockIdx.z : 0;
    int base = EXPERT ? g_off[e] : 0;
    int M    = EXPERT ? (g_off[e + 1] - base) : Mtot;
    int m0   = blockIdx.y * 256;
    if (m0 >= M) return;
    int ntiles = Ncols / 128;
    int sel    = blockIdx.x / ntiles;
    long n0    = (long)(blockIdx.x % ntiles) * 128;
    const float* B = sel ? B1 : B0;
    if (EXPERT) B += (size_t)e * (size_t)K * (size_t)Ncols;
    float* C = sel ? C1 : C0;

    uint32_t sb = (smem_u32(smraw) + 1023u) & ~1023u;

    // ---- producer mappings
    // A: thread handles rows rbase+32r (r=0..7), 16B chunk kq along k
    int rbase = tid >> 3;
    int akq   = (tid & 7);              // 16B chunk index (4 floats each)
    int arows[8];
    #pragma unroll
    for (int r = 0; r < 8; r++) {
        int row = m0 + rbase + 32 * r;
        row = row < M ? row : (M - 1);
        arows[r] = GATHER ? g_tok[base + row] : (base + row);
    }
    // B: warp w covers k rows w*4..w*4+3; per k row, 4 chunks of 32 n
    int bw = wid << 2;

    int nst = K >> 5;
    float acc[4][8][4];
    #pragma unroll
    for (int i = 0; i < 4; i++)
        #pragma unroll
        for (int j = 0; j < 8; j++)
            #pragma unroll
            for (int q = 0; q < 4; q++) acc[i][j][q] = 0.f;

    // fill stage s with k-iter `it`
    auto fill = [&](int s, int it) {
        uint32_t aB = sb + (uint32_t)s * STG;
        uint32_t bB = aB + 32768u;
        int k0 = it << 5;
        #pragma unroll
        for (int r = 0; r < 8; r++) {
            const float* src = A + (size_t)arows[r] * K + k0 + akq * 4;
            uint32_t dst = aB + SWZ((uint32_t)((rbase + 32 * r) * 128 + akq * 16));
            cpa16(dst, src);
        }
        #pragma unroll
        for (int o = 0; o < 16; o++) {
            int kk = bw + (o >> 2);
            int n  = ((o & 3) << 5) + lane;
            const float* src = B + (size_t)(k0 + kk) * Ncols + n0 + n;
            uint32_t dst = bB + SWZ((uint32_t)(n * 128 + kk * 4));
            cpa4(dst, src);
        }
    };

    fill(0, 0); CPA_COMMIT();
    if (nst > 1) fill(1, 1);
    CPA_COMMIT();

    for (int it = 0; it < nst; it++) {
        int s = it % 3;
        CPA_WAIT1();
        __syncthreads();
        if (it + 2 < nst) fill((it + 2) % 3, it + 2);
        CPA_COMMIT();

        uint32_t aB = sb + (uint32_t)s * STG;
        uint32_t bB = aB + 32768u;
        #pragma unroll
        for (int ks = 0; ks < 4; ks++) {
            uint32_t af[4][4];
            #pragma unroll
            for (int mf = 0; mf < 4; mf++) {
                uint32_t row = (uint32_t)(wm * 64 + mf * 16 + (lane & 15));
                uint32_t off = row * 128 + (uint32_t)ks * 32 + ((lane >> 4) * 16);
                ldsm4(af[mf], aB + SWZ(off));
            }
            uint32_t bf[4][4];
            #pragma unroll
            for (int j = 0; j < 4; j++) {
                uint32_t row = (uint32_t)(wn * 64 + j * 16 + (lane & 7) + ((lane >> 4) << 3));
                uint32_t off = row * 128 + (uint32_t)ks * 32 + (((lane >> 3) & 1) * 16);
                ldsm4(bf[j], bB + SWZ(off));
            }
            #pragma unroll
            for (int mf = 0; mf < 4; mf++)
                #pragma unroll
                for (int nf = 0; nf < 8; nf++)
                    mma_tf32(acc[mf][nf], af[mf], bf[nf >> 1][(nf & 1) * 2],
                             bf[nf >> 1][(nf & 1) * 2 + 1]);
        }
    }

    // ---- epilogue
    #pragma unroll
    for (int mf = 0; mf < 4; mf++) {
        int r0 = m0 + wm * 64 + mf * 16 + (lane >> 2);
        #pragma unroll
        for (int nf = 0; nf < 8; nf++) {
            long col = n0 + wn * 64 + nf * 8 + (lane & 3) * 2;
            float* cp = C + (size_t)(base + r0) * Ncols + col;
            if (r0 < M)     *(float2*)cp                       = make_float2(acc[mf][nf][0], acc[mf][nf][1]);
            if (r0 + 8 < M) *(float2*)(cp + (size_t)8 * Ncols) = make_float2(acc[mf][nf][2], acc[mf][nf][3]);
        }
    }
}

// ---------------- elementwise ----------------
// t = silu(g)*u, output rounded to tf32-RN bits (feeds the down GEMM as A)
__global__ void silu_mul_kernel(float* __restrict__ g, const float* __restrict__ u, size_t nelem) {
    size_t i = ((size_t)blockIdx.x * blockDim.x + threadIdx.x) * 4;
    if (i >= nelem) return;
    float4 gv = *(const float4*)(g + i);
    float4 uv = *(const float4*)(u + i);
    uint4 o;
    o.x = __float_as_uint(gv.x / (1.f + expf(-gv.x)) * uv.x) + 0x1000u;
    o.y = __float_as_uint(gv.y / (1.f + expf(-gv.y)) * uv.y) + 0x1000u;
    o.z = __float_as_uint(gv.z / (1.f + expf(-gv.z)) * uv.z) + 0x1000u;
    o.w = __float_as_uint(gv.w / (1.f + expf(-gv.w)) * uv.w) + 0x1000u;
    *(uint4*)(g + i) = o;
}

__global__ void sgate_kernel(const float* __restrict__ h, const float* __restrict__ w) {
    int gt = blockIdx.x * blockDim.x + threadIdx.x;
    int n = gt >> 5, lane = gt & 31;
    if (n >= NTOK) return;
    const float* hp = h + (size_t)n * HDIM;
    float s = 0.f;
    for (int i = lane; i < HDIM; i += 32) s = fmaf(hp[i], w[i], s);
    #pragma unroll
    for (int o = 16; o; o >>= 1) s += __shfl_xor_sync(0xffffffff, s, o);
    if (lane == 0) g_sg[n] = 1.f / (1.f + expf(-s));
}

__global__ void combine_kernel(float* __restrict__ out) {
    int n = blockIdx.x;
    __shared__ int   ss[TOPK];
    __shared__ float ww[TOPK];
    __shared__ float sgv;
    if (threadIdx.x < TOPK) {
        ss[threadIdx.x] = g_slotof[n * TOPK + threadIdx.x];
        ww[threadIdx.x] = g_topk_w[n * TOPK + threadIdx.x];
    }
    if (threadIdx.x == 0) sgv = g_sg[n];
    __syncthreads();
    const float4* d0 = (const float4*)(g_Dr + (size_t)ss[0] * HDIM);
    const float4* d1 = (const float4*)(g_Dr + (size_t)ss[1] * HDIM);
    const float4* d2 = (const float4*)(g_Dr + (size_t)ss[2] * HDIM);
    const float4* d3 = (const float4*)(g_Dr + (size_t)ss[3] * HDIM);
    const float4* sh = (const float4*)(g_Ss + (size_t)n * HDIM);
    float4* op = (float4*)(out + (size_t)n * HDIM);
    float w0 = ww[0], w1 = ww[1], w2 = ww[2], w3 = ww[3], s = sgv;
    for (int j = threadIdx.x; j < HDIM / 4; j += blockDim.x) {
        float4 a = d0[j], b = d1[j], c = d2[j], d = d3[j], e2 = sh[j];
        float4 r;
        r.x = w0 * a.x + w1 * b.x + w2 * c.x + w3 * d.x + s * e2.x;
        r.y = w0 * a.y + w1 * b.y + w2 * c.y + w3 * d.y + s * e2.y;
        r.z = w0 * a.z + w1 * b.z + w2 * c.z + w3 * d.z + s * e2.z;
        r.w = w0 * a.w + w1 * b.w + w2 * c.w + w3 * d.w + s * e2.w;
        op[j] = r;
    }
}

// ---------------- launch ----------------
extern "C" void kernel_launch(void* const* d_in, const int* in_sizes, int n_in,
                              void* d_out, int out_size) {
    const float* h   = (const float*)d_in[0];
    const float* rw  = (const float*)d_in[1];
    const float* wg  = (const float*)d_in[2];
    const float* wu  = (const float*)d_in[3];
    const float* wd  = (const float*)d_in[4];
    const float* shg = (const float*)d_in[5];
    const float* shu = (const float*)d_in[6];
    const float* shd = (const float*)d_in[7];
    const float* sgw = (const float*)d_in[8];
    float* out = (float*)d_out;

    float *pGr, *pUr, *pDr, *pGs, *pUs, *pSs, *pHr;
    float *pWg, *pWu, *pWd, *pSg, *pSu, *pSd;
    cudaGetSymbolAddress((void**)&pGr, g_Gr);
    cudaGetSymbolAddress((void**)&pUr, g_Ur);
    cudaGetSymbolAddress((void**)&pDr, g_Dr);
    cudaGetSymbolAddress((void**)&pGs, g_Gs);
    cudaGetSymbolAddress((void**)&pUs, g_Us);
    cudaGetSymbolAddress((void**)&pSs, g_Ss);
    cudaGetSymbolAddress((void**)&pHr, g_hr);
    cudaGetSymbolAddress((void**)&pWg, g_wg);
    cudaGetSymbolAddress((void**)&pWu, g_wu);
    cudaGetSymbolAddress((void**)&pWd, g_wd);
    cudaGetSymbolAddress((void**)&pSg, g_shg);
    cudaGetSymbolAddress((void**)&pSu, g_shu);
    cudaGetSymbolAddress((void**)&pSd, g_shd);

    const int SMB = 3 * 49152 + 1024;  // 148480
    cudaFuncSetAttribute(mmagemm<true,  true >, cudaFuncAttributeMaxDynamicSharedMemorySize, SMB);
    cudaFuncSetAttribute(mmagemm<false, true >, cudaFuncAttributeMaxDynamicSharedMemorySize, SMB);
    cudaFuncSetAttribute(mmagemm<false, false>, cudaFuncAttributeMaxDynamicSharedMemorySize, SMB);

    // Pre-round all GEMM operands to tf32-RN (counts divisible by 1024 floats)
    {
        const size_t NW = (size_t)NEXP * HDIM * IMOE;      // 46,137,344
        const size_t NS = (size_t)HDIM * ISH;              // 11,534,336
        const size_t NH = (size_t)NTOK * HDIM;             // 8,388,608
        round_kernel<<<(unsigned)(NH / 4 / 256), 256>>>(h,   pHr);
        round_kernel<<<(unsigned)(NW / 4 / 256), 256>>>(wg,  pWg);
        round_kernel<<<(unsigned)(NW / 4 / 256), 256>>>(wu,  pWu);
        round_kernel<<<(unsigned)(NW / 4 / 256), 256>>>(wd,  pWd);
        round_kernel<<<(unsigned)(NS / 4 / 256), 256>>>(shg, pSg);
        round_kernel<<<(unsigned)(NS / 4 / 256), 256>>>(shu, pSu);
        round_kernel<<<(unsigned)(NS / 4 / 256), 256>>>(shd, pSd);
    }

    // Router pipeline
    init_kernel<<<1, 32>>>();
    router_kernel<<<NTOK, 128>>>(h, rw);
    offsets_kernel<<<1, 1>>>();
    scatter_kernel<<<NSLOT / 256, 256>>>();

    // Routed experts: fused gate+up (gathered A), SwiGLU, down
    {
        dim3 g(2 * (IMOE / 128), 16, NEXP);   // (22, 16, 16)
        mmagemm<true, true><<<g, 256, SMB>>>(pHr, pWg, pWu, pGr, pUr, IMOE, HDIM, 0);
    }
    {
        size_t ne = (size_t)NSLOT * IMOE;
        silu_mul_kernel<<<(unsigned)(ne / 4 / 256), 256>>>(pGr, pUr, ne);
    }
    {
        dim3 g(HDIM / 128, 16, NEXP);         // (16, 16, 16)
        mmagemm<false, true><<<g, 256, SMB>>>(pGr, pWd, pWd, pDr, pDr, HDIM, IMOE, 0);
    }

    // Shared expert: fused gate+up, SwiGLU, down
    {
        dim3 g(2 * (ISH / 128), NTOK / 256, 1);   // (88, 16, 1)
        mmagemm<false, false><<<g, 256, SMB>>>(pHr, pSg, pSu, pGs, pUs, ISH, HDIM, NTOK);
    }
    {
        size_t ne = (size_t)NTOK * ISH;
        silu_mul_kernel<<<(unsigned)(ne / 4 / 256), 256>>>(pGs, pUs, ne);
    }
    {
        dim3 g(HDIM / 128, NTOK / 256, 1);    // (16, 16, 1)
        mmagemm<false, false><<<g, 256, SMB>>>(pGs, pSd, pSd, pSs, pSs, HDIM, ISH, NTOK);
    }

    sgate_kernel<<<(NTOK * 32 + 255) / 256, 256>>>(h, sgw);
    combine_kernel<<<NTOK, 256>>>(out);
}

// round 11
// speedup vs baseline: 3.8579x; 1.1262x over previous
#include <cuda_runtime.h>
#include <math.h>
#include <stdint.h>

// Problem shapes (fixed)
#define NTOK 4096
#define HDIM 2048
#define NEXP 16
#define TOPK 4
#define IMOE 1408
#define ISH  5632
#define NSLOT (NTOK*TOPK)

// ---------------- scratch (device globals) ----------------
__device__ float g_Gr[(size_t)NSLOT * IMOE];
__device__ float g_Ur[(size_t)NSLOT * IMOE];
__device__ float g_Dr[(size_t)NSLOT * HDIM];
__device__ float g_Gs[(size_t)NTOK * ISH];
__device__ float g_Us[(size_t)NTOK * ISH];
__device__ float g_Ss[(size_t)NTOK * HDIM];
__device__ float g_sg[NTOK];
__device__ int   g_topk_idx[NSLOT];
__device__ float g_topk_w[NSLOT];
__device__ int   g_cnt[NEXP];
__device__ int   g_off[NEXP + 1];
__device__ int   g_fill[NEXP];
__device__ int   g_tok[NSLOT];
__device__ int   g_slotof[NSLOT];
// pre-rounded copies; weights also TRANSPOSED to [Ncols][K] (n-major)
__device__ float g_hr [(size_t)NTOK * HDIM];
__device__ float g_wg [(size_t)NEXP * IMOE * HDIM];   // [E][I][H]
__device__ float g_wu [(size_t)NEXP * IMOE * HDIM];   // [E][I][H]
__device__ float g_wd [(size_t)NEXP * HDIM * IMOE];   // [E][H][I]
__device__ float g_shg[(size_t)ISH * HDIM];           // [ISH][H]
__device__ float g_shu[(size_t)ISH * HDIM];           // [ISH][H]
__device__ float g_shd[(size_t)HDIM * ISH];           // [H][ISH]

// ---------------- helpers ----------------
#define SWZ(off) ((off) ^ (((off) >> 3) & 0x70))

__device__ __forceinline__ uint32_t smem_u32(const void* p) {
    uint32_t a;
    asm("{ .reg .u64 t; cvta.to.shared.u64 t, %1; cvt.u32.u64 %0, t; }" : "=r"(a) : "l"(p));
    return a;
}
__device__ __forceinline__ void ldsm4(uint32_t* r, uint32_t addr) {
    asm volatile("ldmatrix.sync.aligned.m8n8.x4.shared.b16 {%0,%1,%2,%3}, [%4];"
                 : "=r"(r[0]), "=r"(r[1]), "=r"(r[2]), "=r"(r[3]) : "r"(addr));
}
__device__ __forceinline__ void mma_tf32(float* c, const uint32_t* a, uint32_t b0, uint32_t b1) {
    asm volatile("mma.sync.aligned.m16n8k8.row.col.f32.tf32.tf32.f32 "
                 "{%0,%1,%2,%3}, {%4,%5,%6,%7}, {%8,%9}, {%0,%1,%2,%3};"
                 : "+f"(c[0]), "+f"(c[1]), "+f"(c[2]), "+f"(c[3])
                 : "r"(a[0]), "r"(a[1]), "r"(a[2]), "r"(a[3]), "r"(b0), "r"(b1));
}
__device__ __forceinline__ void cpa16(uint32_t dst, const void* src) {
    asm volatile("cp.async.cg.shared.global [%0], [%1], 16;" :: "r"(dst), "l"(src));
}
#define CPA_COMMIT() asm volatile("cp.async.commit_group;" ::: "memory")
#define CPA_WAIT1()  asm volatile("cp.async.wait_group 1;" ::: "memory")

// ---------------- small kernels ----------------
__global__ void init_kernel() {
    int t = threadIdx.x;
    if (t < NEXP) { g_cnt[t] = 0; g_fill[t] = 0; }
}

// round only (for h)
__global__ void round_kernel(const float* __restrict__ src, float* __restrict__ dst) {
    size_t i = (size_t)blockIdx.x * blockDim.x + threadIdx.x;
    uint4 v = ((const uint4*)src)[i];
    v.x += 0x1000u; v.y += 0x1000u; v.z += 0x1000u; v.w += 0x1000u;
    ((uint4*)dst)[i] = v;
}

// transpose [R,C] -> [C,R] per z-matrix, with tf32-RN bit rounding
__global__ void tround_kernel(const float* __restrict__ src, float* __restrict__ dst,
                              int R, int C) {
    __shared__ uint32_t tile[32][33];
    size_t mat = (size_t)blockIdx.z * (size_t)R * (size_t)C;
    int c0 = blockIdx.x * 32, r0 = blockIdx.y * 32;
    const uint32_t* s = (const uint32_t*)src + mat;
    uint32_t* d = (uint32_t*)dst + mat;
    int tx = threadIdx.x, ty = threadIdx.y;   // 32 x 8
    #pragma unroll
    for (int i = 0; i < 4; i++) {
        int r = r0 + ty + i * 8;
        tile[ty + i * 8][tx] = s[(size_t)r * C + c0 + tx] + 0x1000u;
    }
    __syncthreads();
    #pragma unroll
    for (int i = 0; i < 4; i++) {
        int c = c0 + ty + i * 8;
        d[(size_t)c * R + r0 + tx] = tile[tx][ty + i * 8];
    }
}

__global__ void router_kernel(const float* __restrict__ h, const float* __restrict__ rw) {
    __shared__ float sh[HDIM];
    __shared__ float lg[NEXP];
    int n = blockIdx.x;
    int tid = threadIdx.x;
    const float* hp = h + (size_t)n * HDIM;
    for (int i = tid; i < HDIM; i += 128) sh[i] = hp[i];
    __syncthreads();
    int w = tid >> 5, lane = tid & 31;
    for (int e = w; e < NEXP; e += 4) {
        const float* r = rw + (size_t)e * HDIM;
        float s = 0.f;
        for (int i = lane; i < HDIM; i += 32) s += sh[i] * r[i];
        #pragma unroll
        for (int o = 16; o; o >>= 1) s += __shfl_xor_sync(0xffffffff, s, o);
        if (lane == 0) lg[e] = s;
    }
    __syncthreads();
    if (tid == 0) {
        float m = -1e30f;
        for (int e = 0; e < NEXP; e++) m = fmaxf(m, lg[e]);
        float p[NEXP]; float sum = 0.f;
        for (int e = 0; e < NEXP; e++) { p[e] = expf(lg[e] - m); sum += p[e]; }
        float inv = 1.f / sum;
        for (int e = 0; e < NEXP; e++) p[e] *= inv;
        int idx[TOPK]; float val[TOPK]; float tot = 0.f;
        for (int k = 0; k < TOPK; k++) {
            float best = -1.f; int bi = 0;
            for (int e = 0; e < NEXP; e++) if (p[e] > best) { best = p[e]; bi = e; }
            idx[k] = bi; val[k] = best; p[bi] = -2.f; tot += best;
        }
        float invt = 1.f / fmaxf(tot, 1e-9f);
        for (int k = 0; k < TOPK; k++) {
            g_topk_idx[n * TOPK + k] = idx[k];
            g_topk_w[n * TOPK + k]   = val[k] * invt;
            atomicAdd(&g_cnt[idx[k]], 1);
        }
    }
}

__global__ void offsets_kernel() {
    if (threadIdx.x == 0) {
        int acc = 0;
        for (int e = 0; e < NEXP; e++) { g_off[e] = acc; acc += g_cnt[e]; }
        g_off[NEXP] = acc;
    }
}

__global__ void scatter_kernel() {
    int i = blockIdx.x * blockDim.x + threadIdx.x;
    if (i >= NSLOT) return;
    int e = g_topk_idx[i];
    int pos = g_off[e] + atomicAdd(&g_fill[e], 1);
    g_tok[pos]  = i / TOPK;
    g_slotof[i] = pos;
}

// ---------------- tf32 mma.sync GEMM, cp.async 3-stage, B pre-transposed ----------------
// C[M,Ncols] = A[M,K] @ B^T where B stored [Ncols][K] (n-major).
// Block tile 256x128x32, 8 warps (4x2), warp tile 64x64 via m16n8k8 tf32 mma.
template <bool GATHER, bool EXPERT>
__global__ void __launch_bounds__(256, 1)
mmagemm(const float* __restrict__ A, const float* __restrict__ B0, const float* __restrict__ B1,
        float* __restrict__ C0, float* __restrict__ C1, int Ncols, int K, int Mtot)
{
    extern __shared__ char smraw[];
    constexpr uint32_t STG = 49152u;
    int tid = threadIdx.x, lane = tid & 31, wid = tid >> 5;
    int wm = wid >> 1, wn = wid & 1;   // 4 x 2 warp grid, warp tile 64x64

    int e    = EXPERT ? blockIdx.z : 0;
    int base = EXPERT ? g_off[e] : 0;
    int M    = EXPERT ? (g_off[e + 1] - base) : Mtot;
    int m0   = blockIdx.y * 256;
    if (m0 >= M) return;
    int ntiles = Ncols / 128;
    int sel    = blockIdx.x / ntiles;
    long n0    = (long)(blockIdx.x % ntiles) * 128;
    const float* B = sel ? B1 : B0;
    if (EXPERT) B += (size_t)e * (size_t)K * (size_t)Ncols;
    float* C = sel ? C1 : C0;

    uint32_t sb = (smem_u32(smraw) + 1023u) & ~1023u;

    // ---- producer mappings (all 16B cp.async along k)
    int rbase = tid >> 3;               // 0..31
    int akq   = (tid & 7);              // 16B chunk index along k
    int arows[8];
    #pragma unroll
    for (int r = 0; r < 8; r++) {
        int row = m0 + rbase + 32 * r;
        row = row < M ? row : (M - 1);
        arows[r] = GATHER ? g_tok[base + row] : (base + row);
    }
    const float* Bbase = B + (size_t)n0 * K;   // tile rows n-major

    int nst = K >> 5;
    float acc[4][8][4];
    #pragma unroll
    for (int i = 0; i < 4; i++)
        #pragma unroll
        for (int j = 0; j < 8; j++)
            #pragma unroll
            for (int q = 0; q < 4; q++) acc[i][j][q] = 0.f;

    auto fill = [&](int s, int it) {
        uint32_t aB = sb + (uint32_t)s * STG;
        uint32_t bB = aB + 32768u;
        int k0 = it << 5;
        #pragma unroll
        for (int r = 0; r < 8; r++) {
            const float* src = A + (size_t)arows[r] * K + k0 + akq * 4;
            uint32_t dst = aB + SWZ((uint32_t)((rbase + 32 * r) * 128 + akq * 16));
            cpa16(dst, src);
        }
        #pragma unroll
        for (int r = 0; r < 4; r++) {
            int row = rbase + 32 * r;   // 0..127
            const float* src = Bbase + (size_t)row * K + k0 + akq * 4;
            uint32_t dst = bB + SWZ((uint32_t)(row * 128 + akq * 16));
            cpa16(dst, src);
        }
    };

    fill(0, 0); CPA_COMMIT();
    if (nst > 1) fill(1, 1);
    CPA_COMMIT();

    for (int it = 0; it < nst; it++) {
        int s = it % 3;
        CPA_WAIT1();
        __syncthreads();
        if (it + 2 < nst) fill((it + 2) % 3, it + 2);
        CPA_COMMIT();

        uint32_t aB = sb + (uint32_t)s * STG;
        uint32_t bB = aB + 32768u;
        #pragma unroll
        for (int ks = 0; ks < 4; ks++) {
            uint32_t af[4][4];
            #pragma unroll
            for (int mf = 0; mf < 4; mf++) {
                uint32_t row = (uint32_t)(wm * 64 + mf * 16 + (lane & 15));
                uint32_t off = row * 128 + (uint32_t)ks * 32 + ((lane >> 4) * 16);
                ldsm4(af[mf], aB + SWZ(off));
            }
            uint32_t bf[4][4];
            #pragma unroll
            for (int j = 0; j < 4; j++) {
                uint32_t row = (uint32_t)(wn * 64 + j * 16 + (lane & 7) + ((lane >> 4) << 3));
                uint32_t off = row * 128 + (uint32_t)ks * 32 + (((lane >> 3) & 1) * 16);
                ldsm4(bf[j], bB + SWZ(off));
            }
            #pragma unroll
            for (int mf = 0; mf < 4; mf++)
                #pragma unroll
                for (int nf = 0; nf < 8; nf++)
                    mma_tf32(acc[mf][nf], af[mf], bf[nf >> 1][(nf & 1) * 2],
                             bf[nf >> 1][(nf & 1) * 2 + 1]);
        }
    }

    // ---- epilogue
    #pragma unroll
    for (int mf = 0; mf < 4; mf++) {
        int r0 = m0 + wm * 64 + mf * 16 + (lane >> 2);
        #pragma unroll
        for (int nf = 0; nf < 8; nf++) {
            long col = n0 + wn * 64 + nf * 8 + (lane & 3) * 2;
            float* cp = C + (size_t)(base + r0) * Ncols + col;
            if (r0 < M)     *(float2*)cp                       = make_float2(acc[mf][nf][0], acc[mf][nf][1]);
            if (r0 + 8 < M) *(float2*)(cp + (size_t)8 * Ncols) = make_float2(acc[mf][nf][2], acc[mf][nf][3]);
        }
    }
}

// ---------------- elementwise ----------------
__global__ void silu_mul_kernel(float* __restrict__ g, const float* __restrict__ u, size_t nelem) {
    size_t i = ((size_t)blockIdx.x * blockDim.x + threadIdx.x) * 4;
    if (i >= nelem) return;
    float4 gv = *(const float4*)(g + i);
    float4 uv = *(const float4*)(u + i);
    uint4 o;
    o.x = __float_as_uint(gv.x / (1.f + expf(-gv.x)) * uv.x) + 0x1000u;
    o.y = __float_as_uint(gv.y / (1.f + expf(-gv.y)) * uv.y) + 0x1000u;
    o.z = __float_as_uint(gv.z / (1.f + expf(-gv.z)) * uv.z) + 0x1000u;
    o.w = __float_as_uint(gv.w / (1.f + expf(-gv.w)) * uv.w) + 0x1000u;
    *(uint4*)(g + i) = o;
}

__global__ void sgate_kernel(const float* __restrict__ h, const float* __restrict__ w) {
    int gt = blockIdx.x * blockDim.x + threadIdx.x;
    int n = gt >> 5, lane = gt & 31;
    if (n >= NTOK) return;
    const float* hp = h + (size_t)n * HDIM;
    float s = 0.f;
    for (int i = lane; i < HDIM; i += 32) s = fmaf(hp[i], w[i], s);
    #pragma unroll
    for (int o = 16; o; o >>= 1) s += __shfl_xor_sync(0xffffffff, s, o);
    if (lane == 0) g_sg[n] = 1.f / (1.f + expf(-s));
}

__global__ void combine_kernel(float* __restrict__ out) {
    int n = blockIdx.x;
    __shared__ int   ss[TOPK];
    __shared__ float ww[TOPK];
    __shared__ float sgv;
    if (threadIdx.x < TOPK) {
        ss[threadIdx.x] = g_slotof[n * TOPK + threadIdx.x];
        ww[threadIdx.x] = g_topk_w[n * TOPK + threadIdx.x];
    }
    if (threadIdx.x == 0) sgv = g_sg[n];
    __syncthreads();
    const float4* d0 = (const float4*)(g_Dr + (size_t)ss[0] * HDIM);
    const float4* d1 = (const float4*)(g_Dr + (size_t)ss[1] * HDIM);
    const float4* d2 = (const float4*)(g_Dr + (size_t)ss[2] * HDIM);
    const float4* d3 = (const float4*)(g_Dr + (size_t)ss[3] * HDIM);
    const float4* sh = (const float4*)(g_Ss + (size_t)n * HDIM);
    float4* op = (float4*)(out + (size_t)n * HDIM);
    float w0 = ww[0], w1 = ww[1], w2 = ww[2], w3 = ww[3], s = sgv;
    for (int j = threadIdx.x; j < HDIM / 4; j += blockDim.x) {
        float4 a = d0[j], b = d1[j], c = d2[j], d = d3[j], e2 = sh[j];
        float4 r;
        r.x = w0 * a.x + w1 * b.x + w2 * c.x + w3 * d.x + s * e2.x;
        r.y = w0 * a.y + w1 * b.y + w2 * c.y + w3 * d.y + s * e2.y;
        r.z = w0 * a.z + w1 * b.z + w2 * c.z + w3 * d.z + s * e2.z;
        r.w = w0 * a.w + w1 * b.w + w2 * c.w + w3 * d.w + s * e2.w;
        op[j] = r;
    }
}

// ---------------- launch ----------------
extern "C" void kernel_launch(void* const* d_in, const int* in_sizes, int n_in,
                              void* d_out, int out_size) {
    const float* h   = (const float*)d_in[0];
    const float* rw  = (const float*)d_in[1];
    const float* wg  = (const float*)d_in[2];
    const float* wu  = (const float*)d_in[3];
    const float* wd  = (const float*)d_in[4];
    const float* shg = (const float*)d_in[5];
    const float* shu = (const float*)d_in[6];
    const float* shd = (const float*)d_in[7];
    const float* sgw = (const float*)d_in[8];
    float* out = (float*)d_out;

    float *pGr, *pUr, *pDr, *pGs, *pUs, *pSs, *pHr;
    float *pWg, *pWu, *pWd, *pSg, *pSu, *pSd;
    cudaGetSymbolAddress((void**)&pGr, g_Gr);
    cudaGetSymbolAddress((void**)&pUr, g_Ur);
    cudaGetSymbolAddress((void**)&pDr, g_Dr);
    cudaGetSymbolAddress((void**)&pGs, g_Gs);
    cudaGetSymbolAddress((void**)&pUs, g_Us);
    cudaGetSymbolAddress((void**)&pSs, g_Ss);
    cudaGetSymbolAddress((void**)&pHr, g_hr);
    cudaGetSymbolAddress((void**)&pWg, g_wg);
    cudaGetSymbolAddress((void**)&pWu, g_wu);
    cudaGetSymbolAddress((void**)&pWd, g_wd);
    cudaGetSymbolAddress((void**)&pSg, g_shg);
    cudaGetSymbolAddress((void**)&pSu, g_shu);
    cudaGetSymbolAddress((void**)&pSd, g_shd);

    const int SMB = 3 * 49152 + 1024;  // 148480
    cudaFuncSetAttribute(mmagemm<true,  true >, cudaFuncAttributeMaxDynamicSharedMemorySize, SMB);
    cudaFuncSetAttribute(mmagemm<false, true >, cudaFuncAttributeMaxDynamicSharedMemorySize, SMB);
    cudaFuncSetAttribute(mmagemm<false, false>, cudaFuncAttributeMaxDynamicSharedMemorySize, SMB);

    // Pre-round h; pre-round + transpose all weight matrices to [Ncols][K]
    {
        const size_t NH = (size_t)NTOK * HDIM;
        round_kernel<<<(unsigned)(NH / 4 / 256), 256>>>(h, pHr);
        dim3 thr(32, 8);
        tround_kernel<<<dim3(IMOE / 32, HDIM / 32, NEXP), thr>>>(wg,  pWg, HDIM, IMOE);
        tround_kernel<<<dim3(IMOE / 32, HDIM / 32, NEXP), thr>>>(wu,  pWu, HDIM, IMOE);
        tround_kernel<<<dim3(HDIM / 32, IMOE / 32, NEXP), thr>>>(wd,  pWd, IMOE, HDIM);
        tround_kernel<<<dim3(ISH / 32,  HDIM / 32, 1),    thr>>>(shg, pSg, HDIM, ISH);
        tround_kernel<<<dim3(ISH / 32,  HDIM / 32, 1),    thr>>>(shu, pSu, HDIM, ISH);
        tround_kernel<<<dim3(HDIM / 32, ISH / 32,  1),    thr>>>(shd, pSd, ISH,  HDIM);
    }

    // Router pipeline
    init_kernel<<<1, 32>>>();
    router_kernel<<<NTOK, 128>>>(h, rw);
    offsets_kernel<<<1, 1>>>();
    scatter_kernel<<<NSLOT / 256, 256>>>();

    // Routed experts: fused gate+up (gathered A), SwiGLU, down
    {
        dim3 g(2 * (IMOE / 128), 16, NEXP);   // (22, 16, 16)
        mmagemm<true, true><<<g, 256, SMB>>>(pHr, pWg, pWu, pGr, pUr, IMOE, HDIM, 0);
    }
    {
        size_t ne = (size_t)NSLOT * IMOE;
        silu_mul_kernel<<<(unsigned)(ne / 4 / 256), 256>>>(pGr, pUr, ne);
    }
    {
        dim3 g(HDIM / 128, 16, NEXP);         // (16, 16, 16)
        mmagemm<false, true><<<g, 256, SMB>>>(pGr, pWd, pWd, pDr, pDr, HDIM, IMOE, 0);
    }

    // Shared expert: fused gate+up, SwiGLU, down
    {
        dim3 g(2 * (ISH / 128), NTOK / 256, 1);   // (88, 16, 1)
        mmagemm<false, false><<<g, 256, SMB>>>(pHr, pSg, pSu, pGs, pUs, ISH, HDIM, NTOK);
    }
    {
        size_t ne = (size_t)NTOK * ISH;
        silu_mul_kernel<<<(unsigned)(ne / 4 / 256), 256>>>(pGs, pUs, ne);
    }
    {
        dim3 g(HDIM / 128, NTOK / 256, 1);    // (16, 16, 1)
        mmagemm<false, false><<<g, 256, SMB>>>(pGs, pSd, pSd, pSs, pSs, HDIM, ISH, NTOK);
    }

    sgate_kernel<<<(NTOK * 32 + 255) / 256, 256>>>(h, sgw);
    combine_kernel<<<NTOK, 256>>>(out);
}

// round 13
// speedup vs baseline: 4.0923x; 1.0608x over previous
#include <cuda_runtime.h>
#include <math.h>
#include <stdint.h>

// Problem shapes (fixed)
#define NTOK 4096
#define HDIM 2048
#define NEXP 16
#define TOPK 4
#define IMOE 1408
#define ISH  5632
#define NSLOT (NTOK*TOPK)

// ---------------- scratch (device globals) ----------------
__device__ float g_Gr[(size_t)NSLOT * IMOE];
__device__ float g_Ur[(size_t)NSLOT * IMOE];
__device__ float g_Dr[(size_t)NSLOT * HDIM];
__device__ float g_Gs[(size_t)NTOK * ISH];
__device__ float g_Us[(size_t)NTOK * ISH];
__device__ float g_Ss[(size_t)NTOK * HDIM];
__device__ float g_sg[NTOK];
__device__ int   g_topk_idx[NSLOT];
__device__ float g_topk_w[NSLOT];
__device__ int   g_cnt[NEXP];
__device__ int   g_off[NEXP + 1];
__device__ int   g_fill[NEXP];
__device__ int   g_tok[NSLOT];
__device__ int   g_slotof[NSLOT];
// pre-rounded copies; weights also TRANSPOSED to [Ncols][K] (n-major)
__device__ float g_hr [(size_t)NTOK * HDIM];
__device__ float g_wg [(size_t)NEXP * IMOE * HDIM];   // [E][I][H]
__device__ float g_wu [(size_t)NEXP * IMOE * HDIM];   // [E][I][H]
__device__ float g_wd [(size_t)NEXP * HDIM * IMOE];   // [E][H][I]
__device__ float g_shg[(size_t)ISH * HDIM];           // [ISH][H]
__device__ float g_shu[(size_t)ISH * HDIM];           // [ISH][H]
__device__ float g_shd[(size_t)HDIM * ISH];           // [H][ISH]

// ---------------- helpers ----------------
#define SWZ(off) ((off) ^ (((off) >> 3) & 0x70))

__device__ __forceinline__ uint32_t smem_u32(const void* p) {
    uint32_t a;
    asm("{ .reg .u64 t; cvta.to.shared.u64 t, %1; cvt.u32.u64 %0, t; }" : "=r"(a) : "l"(p));
    return a;
}
__device__ __forceinline__ void ldsm4(uint32_t* r, uint32_t addr) {
    asm volatile("ldmatrix.sync.aligned.m8n8.x4.shared.b16 {%0,%1,%2,%3}, [%4];"
                 : "=r"(r[0]), "=r"(r[1]), "=r"(r[2]), "=r"(r[3]) : "r"(addr));
}
__device__ __forceinline__ void mma_tf32(float* c, const uint32_t* a, uint32_t b0, uint32_t b1) {
    asm volatile("mma.sync.aligned.m16n8k8.row.col.f32.tf32.tf32.f32 "
                 "{%0,%1,%2,%3}, {%4,%5,%6,%7}, {%8,%9}, {%0,%1,%2,%3};"
                 : "+f"(c[0]), "+f"(c[1]), "+f"(c[2]), "+f"(c[3])
                 : "r"(a[0]), "r"(a[1]), "r"(a[2]), "r"(a[3]), "r"(b0), "r"(b1));
}
__device__ __forceinline__ void cpa16(uint32_t dst, const void* src) {
    asm volatile("cp.async.cg.shared.global [%0], [%1], 16;" :: "r"(dst), "l"(src));
}
#define CPA_COMMIT() asm volatile("cp.async.commit_group;" ::: "memory")
#define CPA_WAIT2()  asm volatile("cp.async.wait_group 2;" ::: "memory")

// ---------------- small kernels ----------------
__global__ void init_kernel() {
    int t = threadIdx.x;
    if (t < NEXP) { g_cnt[t] = 0; g_fill[t] = 0; }
}

// round only (for h)
__global__ void round_kernel(const float* __restrict__ src, float* __restrict__ dst) {
    size_t i = (size_t)blockIdx.x * blockDim.x + threadIdx.x;
    uint4 v = ((const uint4*)src)[i];
    v.x += 0x1000u; v.y += 0x1000u; v.z += 0x1000u; v.w += 0x1000u;
    ((uint4*)dst)[i] = v;
}

// transpose [R,C] -> [C,R] per z-matrix, with tf32-RN bit rounding
__global__ void tround_kernel(const float* __restrict__ src, float* __restrict__ dst,
                              int R, int C) {
    __shared__ uint32_t tile[32][33];
    size_t mat = (size_t)blockIdx.z * (size_t)R * (size_t)C;
    int c0 = blockIdx.x * 32, r0 = blockIdx.y * 32;
    const uint32_t* s = (const uint32_t*)src + mat;
    uint32_t* d = (uint32_t*)dst + mat;
    int tx = threadIdx.x, ty = threadIdx.y;   // 32 x 8
    #pragma unroll
    for (int i = 0; i < 4; i++) {
        int r = r0 + ty + i * 8;
        tile[ty + i * 8][tx] = s[(size_t)r * C + c0 + tx] + 0x1000u;
    }
    __syncthreads();
    #pragma unroll
    for (int i = 0; i < 4; i++) {
        int c = c0 + ty + i * 8;
        d[(size_t)c * R + r0 + tx] = tile[tx][ty + i * 8];
    }
}

__global__ void router_kernel(const float* __restrict__ h, const float* __restrict__ rw) {
    __shared__ float sh[HDIM];
    __shared__ float lg[NEXP];
    int n = blockIdx.x;
    int tid = threadIdx.x;
    const float* hp = h + (size_t)n * HDIM;
    for (int i = tid; i < HDIM; i += 128) sh[i] = hp[i];
    __syncthreads();
    int w = tid >> 5, lane = tid & 31;
    for (int e = w; e < NEXP; e += 4) {
        const float* r = rw + (size_t)e * HDIM;
        float s = 0.f;
        for (int i = lane; i < HDIM; i += 32) s += sh[i] * r[i];
        #pragma unroll
        for (int o = 16; o; o >>= 1) s += __shfl_xor_sync(0xffffffff, s, o);
        if (lane == 0) lg[e] = s;
    }
    __syncthreads();
    if (tid == 0) {
        float m = -1e30f;
        for (int e = 0; e < NEXP; e++) m = fmaxf(m, lg[e]);
        float p[NEXP]; float sum = 0.f;
        for (int e = 0; e < NEXP; e++) { p[e] = expf(lg[e] - m); sum += p[e]; }
        float inv = 1.f / sum;
        for (int e = 0; e < NEXP; e++) p[e] *= inv;
        int idx[TOPK]; float val[TOPK]; float tot = 0.f;
        for (int k = 0; k < TOPK; k++) {
            float best = -1.f; int bi = 0;
            for (int e = 0; e < NEXP; e++) if (p[e] > best) { best = p[e]; bi = e; }
            idx[k] = bi; val[k] = best; p[bi] = -2.f; tot += best;
        }
        float invt = 1.f / fmaxf(tot, 1e-9f);
        for (int k = 0; k < TOPK; k++) {
            g_topk_idx[n * TOPK + k] = idx[k];
            g_topk_w[n * TOPK + k]   = val[k] * invt;
            atomicAdd(&g_cnt[idx[k]], 1);
        }
    }
}

__global__ void offsets_kernel() {
    if (threadIdx.x == 0) {
        int acc = 0;
        for (int e = 0; e < NEXP; e++) { g_off[e] = acc; acc += g_cnt[e]; }
        g_off[NEXP] = acc;
    }
}

__global__ void scatter_kernel() {
    int i = blockIdx.x * blockDim.x + threadIdx.x;
    if (i >= NSLOT) return;
    int e = g_topk_idx[i];
    int pos = g_off[e] + atomicAdd(&g_fill[e], 1);
    g_tok[pos]  = i / TOPK;
    g_slotof[i] = pos;
}

// ---------------- tf32 mma.sync GEMM, cp.async 4-stage, B pre-transposed ----------------
// C[M,Ncols] = A[M,K] @ B^T where B stored [Ncols][K] (n-major).
// Block tile 256x128x32, 8 warps (4x2), warp tile 64x64 via m16n8k8 tf32 mma.
template <bool GATHER, bool EXPERT>
__global__ void __launch_bounds__(256, 1)
mmagemm(const float* __restrict__ A, const float* __restrict__ B0, const float* __restrict__ B1,
        float* __restrict__ C0, float* __restrict__ C1, int Ncols, int K, int Mtot)
{
    extern __shared__ char smraw[];
    constexpr uint32_t STG = 49152u;
    int tid = threadIdx.x, lane = tid & 31, wid = tid >> 5;
    int wm = wid >> 1, wn = wid & 1;   // 4 x 2 warp grid, warp tile 64x64

    int e    = EXPERT ? blockIdx.z : 0;
    int base = EXPERT ? g_off[e] : 0;
    int M    = EXPERT ? (g_off[e + 1] - base) : Mtot;
    int m0   = blockIdx.y * 256;
    if (m0 >= M) return;
    int ntiles = Ncols / 128;
    int sel    = blockIdx.x / ntiles;
    long n0    = (long)(blockIdx.x % ntiles) * 128;
    const float* B = sel ? B1 : B0;
    if (EXPERT) B += (size_t)e * (size_t)K * (size_t)Ncols;
    float* C = sel ? C1 : C0;

    uint32_t sb = (smem_u32(smraw) + 1023u) & ~1023u;

    // ---- producer mappings (all 16B cp.async along k)
    int rbase = tid >> 3;               // 0..31
    int akq   = (tid & 7);              // 16B chunk index along k
    int arows[8];
    #pragma unroll
    for (int r = 0; r < 8; r++) {
        int row = m0 + rbase + 32 * r;
        row = row < M ? row : (M - 1);
        arows[r] = GATHER ? g_tok[base + row] : (base + row);
    }
    const float* Bbase = B + (size_t)n0 * K;   // tile rows n-major

    int nst = K >> 5;
    float acc[4][8][4];
    #pragma unroll
    for (int i = 0; i < 4; i++)
        #pragma unroll
        for (int j = 0; j < 8; j++)
            #pragma unroll
            for (int q = 0; q < 4; q++) acc[i][j][q] = 0.f;

    auto fill = [&](int s, int it) {
        uint32_t aB = sb + (uint32_t)s * STG;
        uint32_t bB = aB + 32768u;
        int k0 = it << 5;
        #pragma unroll
        for (int r = 0; r < 8; r++) {
            const float* src = A + (size_t)arows[r] * K + k0 + akq * 4;
            uint32_t dst = aB + SWZ((uint32_t)((rbase + 32 * r) * 128 + akq * 16));
            cpa16(dst, src);
        }
        #pragma unroll
        for (int r = 0; r < 4; r++) {
            int row = rbase + 32 * r;   // 0..127
            const float* src = Bbase + (size_t)row * K + k0 + akq * 4;
            uint32_t dst = bB + SWZ((uint32_t)(row * 128 + akq * 16));
            cpa16(dst, src);
        }
    };

    // prefill 3 stages
    fill(0, 0); CPA_COMMIT();
    if (nst > 1) fill(1, 1);
    CPA_COMMIT();
    if (nst > 2) fill(2, 2);
    CPA_COMMIT();

    for (int it = 0; it < nst; it++) {
        int s = it & 3;
        CPA_WAIT2();
        __syncthreads();
        if (it + 3 < nst) fill((it + 3) & 3, it + 3);
        CPA_COMMIT();

        uint32_t aB = sb + (uint32_t)s * STG;
        uint32_t bB = aB + 32768u;
        #pragma unroll
        for (int ks = 0; ks < 4; ks++) {
            uint32_t af[4][4];
            #pragma unroll
            for (int mf = 0; mf < 4; mf++) {
                uint32_t row = (uint32_t)(wm * 64 + mf * 16 + (lane & 15));
                uint32_t off = row * 128 + (uint32_t)ks * 32 + ((lane >> 4) * 16);
                ldsm4(af[mf], aB + SWZ(off));
            }
            uint32_t bf[4][4];
            #pragma unroll
            for (int j = 0; j < 4; j++) {
                uint32_t row = (uint32_t)(wn * 64 + j * 16 + (lane & 7) + ((lane >> 4) << 3));
                uint32_t off = row * 128 + (uint32_t)ks * 32 + (((lane >> 3) & 1) * 16);
                ldsm4(bf[j], bB + SWZ(off));
            }
            #pragma unroll
            for (int mf = 0; mf < 4; mf++)
                #pragma unroll
                for (int nf = 0; nf < 8; nf++)
                    mma_tf32(acc[mf][nf], af[mf], bf[nf >> 1][(nf & 1) * 2],
                             bf[nf >> 1][(nf & 1) * 2 + 1]);
        }
    }

    // ---- epilogue
    #pragma unroll
    for (int mf = 0; mf < 4; mf++) {
        int r0 = m0 + wm * 64 + mf * 16 + (lane >> 2);
        #pragma unroll
        for (int nf = 0; nf < 8; nf++) {
            long col = n0 + wn * 64 + nf * 8 + (lane & 3) * 2;
            float* cp = C + (size_t)(base + r0) * Ncols + col;
            if (r0 < M)     *(float2*)cp                       = make_float2(acc[mf][nf][0], acc[mf][nf][1]);
            if (r0 + 8 < M) *(float2*)(cp + (size_t)8 * Ncols) = make_float2(acc[mf][nf][2], acc[mf][nf][3]);
        }
    }
}

// ---------------- elementwise ----------------
__global__ void silu_mul_kernel(float* __restrict__ g, const float* __restrict__ u, size_t nelem) {
    size_t i = ((size_t)blockIdx.x * blockDim.x + threadIdx.x) * 4;
    if (i >= nelem) return;
    float4 gv = *(const float4*)(g + i);
    float4 uv = *(const float4*)(u + i);
    uint4 o;
    o.x = __float_as_uint(gv.x / (1.f + expf(-gv.x)) * uv.x) + 0x1000u;
    o.y = __float_as_uint(gv.y / (1.f + expf(-gv.y)) * uv.y) + 0x1000u;
    o.z = __float_as_uint(gv.z / (1.f + expf(-gv.z)) * uv.z) + 0x1000u;
    o.w = __float_as_uint(gv.w / (1.f + expf(-gv.w)) * uv.w) + 0x1000u;
    *(uint4*)(g + i) = o;
}

__global__ void sgate_kernel(const float* __restrict__ h, const float* __restrict__ w) {
    int gt = blockIdx.x * blockDim.x + threadIdx.x;
    int n = gt >> 5, lane = gt & 31;
    if (n >= NTOK) return;
    const float* hp = h + (size_t)n * HDIM;
    float s = 0.f;
    for (int i = lane; i < HDIM; i += 32) s = fmaf(hp[i], w[i], s);
    #pragma unroll
    for (int o = 16; o; o >>= 1) s += __shfl_xor_sync(0xffffffff, s, o);
    if (lane == 0) g_sg[n] = 1.f / (1.f + expf(-s));
}

__global__ void combine_kernel(float* __restrict__ out) {
    int n = blockIdx.x;
    __shared__ int   ss[TOPK];
    __shared__ float ww[TOPK];
    __shared__ float sgv;
    if (threadIdx.x < TOPK) {
        ss[threadIdx.x] = g_slotof[n * TOPK + threadIdx.x];
        ww[threadIdx.x] = g_topk_w[n * TOPK + threadIdx.x];
    }
    if (threadIdx.x == 0) sgv = g_sg[n];
    __syncthreads();
    const float4* d0 = (const float4*)(g_Dr + (size_t)ss[0] * HDIM);
    const float4* d1 = (const float4*)(g_Dr + (size_t)ss[1] * HDIM);
    const float4* d2 = (const float4*)(g_Dr + (size_t)ss[2] * HDIM);
    const float4* d3 = (const float4*)(g_Dr + (size_t)ss[3] * HDIM);
    const float4* sh = (const float4*)(g_Ss + (size_t)n * HDIM);
    float4* op = (float4*)(out + (size_t)n * HDIM);
    float w0 = ww[0], w1 = ww[1], w2 = ww[2], w3 = ww[3], s = sgv;
    for (int j = threadIdx.x; j < HDIM / 4; j += blockDim.x) {
        float4 a = d0[j], b = d1[j], c = d2[j], d = d3[j], e2 = sh[j];
        float4 r;
        r.x = w0 * a.x + w1 * b.x + w2 * c.x + w3 * d.x + s * e2.x;
        r.y = w0 * a.y + w1 * b.y + w2 * c.y + w3 * d.y + s * e2.y;
        r.z = w0 * a.z + w1 * b.z + w2 * c.z + w3 * d.z + s * e2.z;
        r.w = w0 * a.w + w1 * b.w + w2 * c.w + w3 * d.w + s * e2.w;
        op[j] = r;
    }
}

// ---------------- launch ----------------
extern "C" void kernel_launch(void* const* d_in, const int* in_sizes, int n_in,
                              void* d_out, int out_size) {
    const float* h   = (const float*)d_in[0];
    const float* rw  = (const float*)d_in[1];
    const float* wg  = (const float*)d_in[2];
    const float* wu  = (const float*)d_in[3];
    const float* wd  = (const float*)d_in[4];
    const float* shg = (const float*)d_in[5];
    const float* shu = (const float*)d_in[6];
    const float* shd = (const float*)d_in[7];
    const float* sgw = (const float*)d_in[8];
    float* out = (float*)d_out;

    float *pGr, *pUr, *pDr, *pGs, *pUs, *pSs, *pHr;
    float *pWg, *pWu, *pWd, *pSg, *pSu, *pSd;
    cudaGetSymbolAddress((void**)&pGr, g_Gr);
    cudaGetSymbolAddress((void**)&pUr, g_Ur);
    cudaGetSymbolAddress((void**)&pDr, g_Dr);
    cudaGetSymbolAddress((void**)&pGs, g_Gs);
    cudaGetSymbolAddress((void**)&pUs, g_Us);
    cudaGetSymbolAddress((void**)&pSs, g_Ss);
    cudaGetSymbolAddress((void**)&pHr, g_hr);
    cudaGetSymbolAddress((void**)&pWg, g_wg);
    cudaGetSymbolAddress((void**)&pWu, g_wu);
    cudaGetSymbolAddress((void**)&pWd, g_wd);
    cudaGetSymbolAddress((void**)&pSg, g_shg);
    cudaGetSymbolAddress((void**)&pSu, g_shu);
    cudaGetSymbolAddress((void**)&pSd, g_shd);

    const int SMB = 4 * 49152 + 1024;  // 197632 (4-stage)
    cudaFuncSetAttribute(mmagemm<true,  true >, cudaFuncAttributeMaxDynamicSharedMemorySize, SMB);
    cudaFuncSetAttribute(mmagemm<false, true >, cudaFuncAttributeMaxDynamicSharedMemorySize, SMB);
    cudaFuncSetAttribute(mmagemm<false, false>, cudaFuncAttributeMaxDynamicSharedMemorySize, SMB);

    // Pre-round h; pre-round + transpose all weight matrices to [Ncols][K]
    {
        const size_t NH = (size_t)NTOK * HDIM;
        round_kernel<<<(unsigned)(NH / 4 / 256), 256>>>(h, pHr);
        dim3 thr(32, 8);
        tround_kernel<<<dim3(IMOE / 32, HDIM / 32, NEXP), thr>>>(wg,  pWg, HDIM, IMOE);
        tround_kernel<<<dim3(IMOE / 32, HDIM / 32, NEXP), thr>>>(wu,  pWu, HDIM, IMOE);
        tround_kernel<<<dim3(HDIM / 32, IMOE / 32, NEXP), thr>>>(wd,  pWd, IMOE, HDIM);
        tround_kernel<<<dim3(ISH / 32,  HDIM / 32, 1),    thr>>>(shg, pSg, HDIM, ISH);
        tround_kernel<<<dim3(ISH / 32,  HDIM / 32, 1),    thr>>>(shu, pSu, HDIM, ISH);
        tround_kernel<<<dim3(HDIM / 32, ISH / 32,  1),    thr>>>(shd, pSd, ISH,  HDIM);
    }

    // Router pipeline
    init_kernel<<<1, 32>>>();
    router_kernel<<<NTOK, 128>>>(h, rw);
    offsets_kernel<<<1, 1>>>();
    scatter_kernel<<<NSLOT / 256, 256>>>();

    // Routed experts: fused gate+up (gathered A), SwiGLU, down
    {
        dim3 g(2 * (IMOE / 128), 16, NEXP);   // (22, 16, 16)
        mmagemm<true, true><<<g, 256, SMB>>>(pHr, pWg, pWu, pGr, pUr, IMOE, HDIM, 0);
    }
    {
        size_t ne = (size_t)NSLOT * IMOE;
        silu_mul_kernel<<<(unsigned)(ne / 4 / 256), 256>>>(pGr, pUr, ne);
    }
    {
        dim3 g(HDIM / 128, 16, NEXP);         // (16, 16, 16)
        mmagemm<false, true><<<g, 256, SMB>>>(pGr, pWd, pWd, pDr, pDr, HDIM, IMOE, 0);
    }

    // Shared expert: fused gate+up, SwiGLU, down
    {
        dim3 g(2 * (ISH / 128), NTOK / 256, 1);   // (88, 16, 1)
        mmagemm<false, false><<<g, 256, SMB>>>(pHr, pSg, pSu, pGs, pUs, ISH, HDIM, NTOK);
    }
    {
        size_t ne = (size_t)NTOK * ISH;
        silu_mul_kernel<<<(unsigned)(ne / 4 / 256), 256>>>(pGs, pUs, ne);
    }
    {
        dim3 g(HDIM / 128, NTOK / 256, 1);    // (16, 16, 1)
        mmagemm<false, false><<<g, 256, SMB>>>(pGs, pSd, pSd, pSs, pSs, HDIM, ISH, NTOK);
    }

    sgate_kernel<<<(NTOK * 32 + 255) / 256, 256>>>(h, sgw);
    combine_kernel<<<NTOK, 256>>>(out);
}